// round 10
// baseline (speedup 1.0000x reference)
#include <cuda_runtime.h>
#include <math.h>

#define KS2      4
#define BASIS    8
#define HIDDEN   16
#define M_NODES  128      // Chebyshev sample nodes for the fit
#define NCOEF    32       // series length (degree 31)

// Chebyshev coefficients of F(t), t = 2*act-1, act = sigmoid(logit).
__device__ float g_coef[NCOEF];

// Post-sigmoid pipeline evaluated directly at a given activation value.
__device__ __forceinline__ float eval_f_act(float a,
                                            const float* __restrict__ basis,
                                            const float* __restrict__ w1,
                                            const float* __restrict__ b1,
                                            const float* __restrict__ w2,
                                            const float* __restrict__ b2)
{
    float feats[BASIS];
#pragma unroll
    for (int b = 0; b < BASIS; ++b) {
        float s = 0.0f;
#pragma unroll
        for (int j = 0; j < KS2; ++j) {
            float d = a - basis[b * KS2 + j];
            s = fmaf(d, d, s);
        }
        feats[b] = expf(-s);   // GAMMA = 1
    }

    float out = b2[0];
#pragma unroll
    for (int i = 0; i < HIDDEN; ++i) {
        float h = b1[i];
#pragma unroll
        for (int b = 0; b < BASIS; ++b)
            h = fmaf(feats[b], w1[b * HIDDEN + i], h);
        out = fmaf(tanhf(h), w2[i], out);
    }
    return out;
}

// One block, M_NODES threads: sample F at Chebyshev nodes, DCT -> coefficients.
__global__ void build_coef_kernel(const float* __restrict__ basis,
                                  const float* __restrict__ w1,
                                  const float* __restrict__ b1,
                                  const float* __restrict__ w2,
                                  const float* __restrict__ b2)
{
    __shared__ float fv[M_NODES];
    int i = threadIdx.x;

    const float PI = 3.14159265358979323846f;
    float theta = PI * ((float)i + 0.5f) / (float)M_NODES;
    float t = cosf(theta);
    float act = 0.5f * (t + 1.0f);          // node in act-space [0,1]
    fv[i] = eval_f_act(act, basis, w1, b1, w2, b2);
    __syncthreads();

    if (i < NCOEF) {
        float s = 0.0f;
        for (int j = 0; j < M_NODES; ++j) {
            float th = PI * ((float)j + 0.5f) / (float)M_NODES;
            s += fv[j] * cosf((float)i * th);
        }
        float scale = (i == 0) ? (1.0f / (float)M_NODES) : (2.0f / (float)M_NODES);
        g_coef[i] = s * scale;
    }
}

// Pure streaming kernel: 4 patches/thread. Per patch: dot4 -> t = tanh(logit/2)
// (2 MUFU) -> Clenshaw evaluation of the Chebyshev series (register coeffs).
// No table, no scattered loads: L1 carries only the float4 stream.
__global__ void __launch_bounds__(256)
patch_kernel(const float* __restrict__ data,
             const float* __restrict__ conv_w,
             const float* __restrict__ conv_b,
             float* __restrict__ out,
             long long N)
{
    float cw0 = __ldg(conv_w + 0);
    float cw1 = __ldg(conv_w + 1);
    float cw2 = __ldg(conv_w + 2);
    float cw3 = __ldg(conv_w + 3);
    float cb  = __ldg(conv_b);

    // Hoisted uniform loads of the 32 coefficients into registers.
    float c[NCOEF];
#pragma unroll
    for (int k = 0; k < NCOEF; ++k)
        c[k] = __ldg(&g_coef[k]);

    long long tdx = (long long)blockIdx.x * blockDim.x + threadIdx.x;
    long long i0  = tdx * 4;

    if (i0 + 4 <= N) {
        const float4* dp = (const float4*)data + i0;
        float4 v[4];
#pragma unroll
        for (int k = 0; k < 4; ++k)
            v[k] = __ldg(dp + k);

        float r[4];
#pragma unroll
        for (int k = 0; k < 4; ++k) {
            float logit = fmaf(v[k].x, cw0,
                          fmaf(v[k].y, cw1,
                          fmaf(v[k].z, cw2,
                          fmaf(v[k].w, cw3, cb))));
            // t = tanh(logit/2), overflow-safe: u = exp(-|logit|) <= 1
            float u = __expf(-fabsf(logit));
            float t = __fdividef(1.0f - u, 1.0f + u);
            t = copysignf(t, logit);
            // Clenshaw: sum_k c_k T_k(t)
            float t2 = t + t;
            float b1v = 0.0f, b2v = 0.0f;
#pragma unroll
            for (int k = NCOEF - 1; k >= 1; --k) {
                float bn = fmaf(t2, b1v, c[k] - b2v);
                b2v = b1v;
                b1v = bn;
            }
            r[k] = fmaf(t, b1v, c[0] - b2v);
        }
        ((float4*)out)[tdx] = make_float4(r[0], r[1], r[2], r[3]);
    } else if (i0 < N) {
        for (long long i = i0; i < N; ++i) {
            float a0 = data[i * 4 + 0];
            float a1 = data[i * 4 + 1];
            float a2 = data[i * 4 + 2];
            float a3 = data[i * 4 + 3];
            float logit = fmaf(a0, cw0, fmaf(a1, cw1, fmaf(a2, cw2, fmaf(a3, cw3, cb))));
            float u = __expf(-fabsf(logit));
            float t = __fdividef(1.0f - u, 1.0f + u);
            t = copysignf(t, logit);
            float t2 = t + t;
            float b1v = 0.0f, b2v = 0.0f;
#pragma unroll
            for (int k = NCOEF - 1; k >= 1; --k) {
                float bn = fmaf(t2, b1v, c[k] - b2v);
                b2v = b1v;
                b1v = bn;
            }
            out[i] = fmaf(t, b1v, c[0] - b2v);
        }
    }
}

extern "C" void kernel_launch(void* const* d_in, const int* in_sizes, int n_in,
                              void* d_out, int out_size)
{
    const float* data   = (const float*)d_in[0];
    const float* conv_w = (const float*)d_in[1];
    const float* conv_b = (const float*)d_in[2];
    const float* basis  = (const float*)d_in[3];
    const float* w1     = (const float*)d_in[4];
    const float* b1     = (const float*)d_in[5];
    const float* w2     = (const float*)d_in[6];
    const float* b2     = (const float*)d_in[7];

    long long N = (long long)in_sizes[0] / KS2;   // in_sizes[0] = N * KS * KS

    // 1) Fit Chebyshev series of F(t) from this run's weights (1 small block).
    build_coef_kernel<<<1, M_NODES>>>(basis, w1, b1, w2, b2);

    // 2) Streaming per-patch kernel, 4 patches per thread, full grid.
    long long nthreads = (N + 3) / 4;
    int threads = 256;
    long long blocks = (nthreads + threads - 1) / threads;
    if (blocks < 1) blocks = 1;
    patch_kernel<<<(unsigned int)blocks, threads>>>(data, conv_w, conv_b,
                                                    (float*)d_out, N);
}

// round 11
// speedup vs baseline: 1.3505x; 1.3505x over previous
#include <cuda_runtime.h>
#include <math.h>

#define KS2      4
#define BASIS    8
#define HIDDEN   16
#define M_NODES  128      // Chebyshev sample nodes
#define NCOEF    24       // polynomial terms (degree 23)

// Monomial coefficients a_0..a_{23} of F(t), t = 2*sigmoid(logit)-1.
__device__ float g_coef[NCOEF];
__constant__ float c_coef[NCOEF];

// Post-sigmoid pipeline at activation value a.
__device__ __forceinline__ float eval_f_act(float a,
                                            const float* __restrict__ basis,
                                            const float* __restrict__ w1,
                                            const float* __restrict__ b1,
                                            const float* __restrict__ w2,
                                            const float* __restrict__ b2)
{
    float feats[BASIS];
#pragma unroll
    for (int b = 0; b < BASIS; ++b) {
        float s = 0.0f;
#pragma unroll
        for (int j = 0; j < KS2; ++j) {
            float d = a - basis[b * KS2 + j];
            s = fmaf(d, d, s);
        }
        feats[b] = expf(-s);   // GAMMA = 1
    }

    float out = b2[0];
#pragma unroll
    for (int i = 0; i < HIDDEN; ++i) {
        float h = b1[i];
#pragma unroll
        for (int b = 0; b < BASIS; ++b)
            h = fmaf(feats[b], w1[b * HIDDEN + i], h);
        out = fmaf(tanhf(h), w2[i], out);
    }
    return out;
}

// One block, 1024 threads:
//  phase 1: threads 0..127 sample F at Chebyshev nodes
//  phase 2: warp w (w < NCOEF) computes Chebyshev coeff w via shfl reduction
//  phase 3: threads 0..23 convert Chebyshev -> monomial (double, smem recurrence)
__global__ void build_coef_kernel(const float* __restrict__ basis,
                                  const float* __restrict__ w1,
                                  const float* __restrict__ b1,
                                  const float* __restrict__ w2,
                                  const float* __restrict__ b2)
{
    __shared__ float  fv[M_NODES];
    __shared__ float  cheb[NCOEF];
    __shared__ double Tprev[NCOEF], Tcur[NCOEF], acc[NCOEF];

    int tid  = threadIdx.x;
    int wid  = tid >> 5;
    int lane = tid & 31;

    if (tid < M_NODES) {
        float t   = cospif(((float)tid + 0.5f) / (float)M_NODES);
        float act = 0.5f * (t + 1.0f);
        fv[tid] = eval_f_act(act, basis, w1, b1, w2, b2);
    }
    __syncthreads();

    if (wid < NCOEF) {
        float s = 0.0f;
#pragma unroll
        for (int r = 0; r < M_NODES / 32; ++r) {
            int j = lane + r * 32;
            s += fv[j] * cospif((float)wid * (((float)j + 0.5f) / (float)M_NODES));
        }
#pragma unroll
        for (int off = 16; off > 0; off >>= 1)
            s += __shfl_down_sync(0xFFFFFFFFu, s, off);
        if (lane == 0) {
            float scale = (wid == 0) ? (1.0f / M_NODES) : (2.0f / M_NODES);
            cheb[wid] = s * scale;
        }
    }
    __syncthreads();

    // Chebyshev -> monomial: T_k = 2t*T_{k-1} - T_{k-2}; acc[p] = sum c_k (T_k)_p
    if (tid < NCOEF) {
        Tprev[tid] = (tid == 0) ? 1.0 : 0.0;   // T_0
        Tcur[tid]  = (tid == 1) ? 1.0 : 0.0;   // T_1
        acc[tid]   = (tid == 0) ? (double)cheb[0]
                   : (tid == 1) ? (double)cheb[1] : 0.0;
    }
    __syncthreads();
    for (int k = 2; k < NCOEF; ++k) {
        double nv = 0.0;
        if (tid < NCOEF)
            nv = 2.0 * (tid > 0 ? Tcur[tid - 1] : 0.0) - Tprev[tid];
        __syncthreads();
        if (tid < NCOEF) {
            Tprev[tid] = Tcur[tid];
            Tcur[tid]  = nv;
            acc[tid]  += (double)cheb[k] * nv;
        }
        __syncthreads();
    }
    if (tid < NCOEF)
        g_coef[tid] = (float)acc[tid];
}

// Streaming kernel, 4 patches/thread. Per patch: dot4 -> t = tanh(logit/2)
// -> even/odd Horner in t^2 with coefficients from __constant__ memory.
// Coefficient-outer loop: each coeff is read ONCE per 4 patches (uniform LDC),
// so L1 carries only the float4 stream.
__global__ void __launch_bounds__(256)
patch_kernel(const float* __restrict__ data,
             const float* __restrict__ conv_w,
             const float* __restrict__ conv_b,
             float* __restrict__ out,
             long long N)
{
    float cw0 = __ldg(conv_w + 0);
    float cw1 = __ldg(conv_w + 1);
    float cw2 = __ldg(conv_w + 2);
    float cw3 = __ldg(conv_w + 3);
    float cb  = __ldg(conv_b);

    long long tdx = (long long)blockIdx.x * blockDim.x + threadIdx.x;
    long long i0  = tdx * 4;

    if (i0 + 4 <= N) {
        const float4* dp = (const float4*)data + i0;
        float4 v[4];
#pragma unroll
        for (int p = 0; p < 4; ++p)
            v[p] = __ldg(dp + p);

        float t[4], t2[4];
#pragma unroll
        for (int p = 0; p < 4; ++p) {
            float logit = fmaf(v[p].x, cw0,
                          fmaf(v[p].y, cw1,
                          fmaf(v[p].z, cw2,
                          fmaf(v[p].w, cw3, cb))));
            float u = __expf(-fabsf(logit));                 // <= 1, no overflow
            float tt = __fdividef(1.0f - u, 1.0f + u);       // tanh(|logit|/2)
            t[p]  = copysignf(tt, logit);
            t2[p] = t[p] * t[p];
        }

        float e[4], o[4];
#pragma unroll
        for (int p = 0; p < 4; ++p) { e[p] = c_coef[22]; o[p] = c_coef[23]; }
#pragma unroll
        for (int k = 10; k >= 0; --k) {
            float ce = c_coef[2 * k];
            float co = c_coef[2 * k + 1];
#pragma unroll
            for (int p = 0; p < 4; ++p) {
                e[p] = fmaf(e[p], t2[p], ce);
                o[p] = fmaf(o[p], t2[p], co);
            }
        }

        float r[4];
#pragma unroll
        for (int p = 0; p < 4; ++p)
            r[p] = fmaf(t[p], o[p], e[p]);

        ((float4*)out)[tdx] = make_float4(r[0], r[1], r[2], r[3]);
    } else if (i0 < N) {
        for (long long i = i0; i < N; ++i) {
            float a0 = data[i * 4 + 0];
            float a1 = data[i * 4 + 1];
            float a2 = data[i * 4 + 2];
            float a3 = data[i * 4 + 3];
            float logit = fmaf(a0, cw0, fmaf(a1, cw1, fmaf(a2, cw2, fmaf(a3, cw3, cb))));
            float u  = __expf(-fabsf(logit));
            float tt = __fdividef(1.0f - u, 1.0f + u);
            float t  = copysignf(tt, logit);
            float t2 = t * t;
            float e = c_coef[22], o = c_coef[23];
#pragma unroll
            for (int k = 10; k >= 0; --k) {
                e = fmaf(e, t2, c_coef[2 * k]);
                o = fmaf(o, t2, c_coef[2 * k + 1]);
            }
            out[i] = fmaf(t, o, e);
        }
    }
}

extern "C" void kernel_launch(void* const* d_in, const int* in_sizes, int n_in,
                              void* d_out, int out_size)
{
    const float* data   = (const float*)d_in[0];
    const float* conv_w = (const float*)d_in[1];
    const float* conv_b = (const float*)d_in[2];
    const float* basis  = (const float*)d_in[3];
    const float* w1     = (const float*)d_in[4];
    const float* b1     = (const float*)d_in[5];
    const float* w2     = (const float*)d_in[6];
    const float* b2     = (const float*)d_in[7];

    long long N = (long long)in_sizes[0] / KS2;   // in_sizes[0] = N * KS * KS

    // 1) Fit monomial coefficients from this run's weights (1 block, fast).
    build_coef_kernel<<<1, 1024>>>(basis, w1, b1, w2, b2);

    // 2) Publish to __constant__ memory (graph-legal async D2D copy).
    void *src = nullptr, *dst = nullptr;
    cudaGetSymbolAddress(&src, g_coef);
    cudaGetSymbolAddress(&dst, c_coef);
    cudaMemcpyAsync(dst, src, NCOEF * sizeof(float), cudaMemcpyDeviceToDevice, 0);

    // 3) Streaming per-patch kernel, 4 patches per thread, full grid.
    long long nthreads = (N + 3) / 4;
    int threads = 256;
    long long blocks = (nthreads + threads - 1) / threads;
    if (blocks < 1) blocks = 1;
    patch_kernel<<<(unsigned int)blocks, threads>>>(data, conv_w, conv_b,
                                                    (float*)d_out, N);
}

// round 12
// speedup vs baseline: 1.4799x; 1.0958x over previous
#include <cuda_runtime.h>
#include <math.h>

#define KS2      4
#define BASIS    8
#define HIDDEN   16
#define M_NODES  128      // Chebyshev sample nodes
#define NCOEF    16       // polynomial terms (degree 15)

// Monomial coefficients a_0..a_{15} of F(t), t = 2*sigmoid(logit)-1.
__device__ float g_coef[NCOEF];

// Post-sigmoid pipeline at activation value a.
__device__ __forceinline__ float eval_f_act(float a,
                                            const float* __restrict__ basis,
                                            const float* __restrict__ w1,
                                            const float* __restrict__ b1,
                                            const float* __restrict__ w2,
                                            const float* __restrict__ b2)
{
    float feats[BASIS];
#pragma unroll
    for (int b = 0; b < BASIS; ++b) {
        float s = 0.0f;
#pragma unroll
        for (int j = 0; j < KS2; ++j) {
            float d = a - basis[b * KS2 + j];
            s = fmaf(d, d, s);
        }
        feats[b] = expf(-s);   // GAMMA = 1
    }

    float out = b2[0];
#pragma unroll
    for (int i = 0; i < HIDDEN; ++i) {
        float h = b1[i];
#pragma unroll
        for (int b = 0; b < BASIS; ++b)
            h = fmaf(feats[b], w1[b * HIDDEN + i], h);
        out = fmaf(tanhf(h), w2[i], out);
    }
    return out;
}

// One block, 512 threads:
//  phase 1: threads 0..127 sample F at Chebyshev nodes
//  phase 2: warp w (w < NCOEF) computes Chebyshev coeff w via shfl reduction
//  phase 3: threads 0..15 convert Chebyshev -> monomial (double, smem recurrence)
__global__ void build_coef_kernel(const float* __restrict__ basis,
                                  const float* __restrict__ w1,
                                  const float* __restrict__ b1,
                                  const float* __restrict__ w2,
                                  const float* __restrict__ b2)
{
    __shared__ float  fv[M_NODES];
    __shared__ float  cheb[NCOEF];
    __shared__ double Tprev[NCOEF], Tcur[NCOEF], acc[NCOEF];

    int tid  = threadIdx.x;
    int wid  = tid >> 5;
    int lane = tid & 31;

    if (tid < M_NODES) {
        float t   = cospif(((float)tid + 0.5f) / (float)M_NODES);
        float act = 0.5f * (t + 1.0f);
        fv[tid] = eval_f_act(act, basis, w1, b1, w2, b2);
    }
    __syncthreads();

    if (wid < NCOEF) {
        float s = 0.0f;
#pragma unroll
        for (int r = 0; r < M_NODES / 32; ++r) {
            int j = lane + r * 32;
            s += fv[j] * cospif((float)wid * (((float)j + 0.5f) / (float)M_NODES));
        }
#pragma unroll
        for (int off = 16; off > 0; off >>= 1)
            s += __shfl_down_sync(0xFFFFFFFFu, s, off);
        if (lane == 0) {
            float scale = (wid == 0) ? (1.0f / M_NODES) : (2.0f / M_NODES);
            cheb[wid] = s * scale;
        }
    }
    __syncthreads();

    // Chebyshev -> monomial: T_k = 2t*T_{k-1} - T_{k-2}; acc[p] = sum c_k (T_k)_p
    if (tid < NCOEF) {
        Tprev[tid] = (tid == 0) ? 1.0 : 0.0;   // T_0
        Tcur[tid]  = (tid == 1) ? 1.0 : 0.0;   // T_1
        acc[tid]   = (tid == 0) ? (double)cheb[0]
                   : (tid == 1) ? (double)cheb[1] : 0.0;
    }
    __syncthreads();
    for (int k = 2; k < NCOEF; ++k) {
        double nv = 0.0;
        if (tid < NCOEF)
            nv = 2.0 * (tid > 0 ? Tcur[tid - 1] : 0.0) - Tprev[tid];
        __syncthreads();
        if (tid < NCOEF) {
            Tprev[tid] = Tcur[tid];
            Tcur[tid]  = nv;
            acc[tid]  += (double)cheb[k] * nv;
        }
        __syncthreads();
    }
    if (tid < NCOEF)
        g_coef[tid] = (float)acc[tid];
}

// Streaming kernel, 4 patches/thread. Per patch: dot4 -> t = tanh(logit/2)
// -> even/odd Horner in t^2, coefficients via LDG broadcast (L1-resident,
// one wavefront per load). No scattered memory anywhere.
__global__ void __launch_bounds__(256)
patch_kernel(const float* __restrict__ data,
             const float* __restrict__ conv_w,
             const float* __restrict__ conv_b,
             float* __restrict__ out,
             long long N)
{
    float cw0 = __ldg(conv_w + 0);
    float cw1 = __ldg(conv_w + 1);
    float cw2 = __ldg(conv_w + 2);
    float cw3 = __ldg(conv_w + 3);
    float cb  = __ldg(conv_b);

    long long tdx = (long long)blockIdx.x * blockDim.x + threadIdx.x;
    long long i0  = tdx * 4;

    if (i0 + 4 <= N) {
        const float4* dp = (const float4*)data + i0;
        float4 v[4];
#pragma unroll
        for (int p = 0; p < 4; ++p)
            v[p] = __ldg(dp + p);

        float t[4], t2[4];
#pragma unroll
        for (int p = 0; p < 4; ++p) {
            float logit = fmaf(v[p].x, cw0,
                          fmaf(v[p].y, cw1,
                          fmaf(v[p].z, cw2,
                          fmaf(v[p].w, cw3, cb))));
            float u = __expf(-fabsf(logit));                 // <= 1, no overflow
            float tt = __fdividef(1.0f - u, 1.0f + u);       // tanh(|logit|/2)
            t[p]  = copysignf(tt, logit);
            t2[p] = t[p] * t[p];
        }

        float e[4], o[4];
        {
            float ce = __ldg(&g_coef[NCOEF - 2]);
            float co = __ldg(&g_coef[NCOEF - 1]);
#pragma unroll
            for (int p = 0; p < 4; ++p) { e[p] = ce; o[p] = co; }
        }
#pragma unroll
        for (int k = NCOEF / 2 - 2; k >= 0; --k) {
            float ce = __ldg(&g_coef[2 * k]);
            float co = __ldg(&g_coef[2 * k + 1]);
#pragma unroll
            for (int p = 0; p < 4; ++p) {
                e[p] = fmaf(e[p], t2[p], ce);
                o[p] = fmaf(o[p], t2[p], co);
            }
        }

        float r[4];
#pragma unroll
        for (int p = 0; p < 4; ++p)
            r[p] = fmaf(t[p], o[p], e[p]);

        ((float4*)out)[tdx] = make_float4(r[0], r[1], r[2], r[3]);
    } else if (i0 < N) {
        for (long long i = i0; i < N; ++i) {
            float a0 = data[i * 4 + 0];
            float a1 = data[i * 4 + 1];
            float a2 = data[i * 4 + 2];
            float a3 = data[i * 4 + 3];
            float logit = fmaf(a0, cw0, fmaf(a1, cw1, fmaf(a2, cw2, fmaf(a3, cw3, cb))));
            float u  = __expf(-fabsf(logit));
            float tt = __fdividef(1.0f - u, 1.0f + u);
            float t  = copysignf(tt, logit);
            float t2 = t * t;
            float e = __ldg(&g_coef[NCOEF - 2]);
            float o = __ldg(&g_coef[NCOEF - 1]);
#pragma unroll
            for (int k = NCOEF / 2 - 2; k >= 0; --k) {
                e = fmaf(e, t2, __ldg(&g_coef[2 * k]));
                o = fmaf(o, t2, __ldg(&g_coef[2 * k + 1]));
            }
            out[i] = fmaf(t, o, e);
        }
    }
}

extern "C" void kernel_launch(void* const* d_in, const int* in_sizes, int n_in,
                              void* d_out, int out_size)
{
    const float* data   = (const float*)d_in[0];
    const float* conv_w = (const float*)d_in[1];
    const float* conv_b = (const float*)d_in[2];
    const float* basis  = (const float*)d_in[3];
    const float* w1     = (const float*)d_in[4];
    const float* b1     = (const float*)d_in[5];
    const float* w2     = (const float*)d_in[6];
    const float* b2     = (const float*)d_in[7];

    long long N = (long long)in_sizes[0] / KS2;   // in_sizes[0] = N * KS * KS

    // 1) Fit monomial coefficients from this run's weights (1 small block).
    build_coef_kernel<<<1, 512>>>(basis, w1, b1, w2, b2);

    // 2) Streaming per-patch kernel, 4 patches per thread, full grid.
    long long nthreads = (N + 3) / 4;
    int threads = 256;
    long long blocks = (nthreads + threads - 1) / threads;
    if (blocks < 1) blocks = 1;
    patch_kernel<<<(unsigned int)blocks, threads>>>(data, conv_w, conv_b,
                                                    (float*)d_out, N);
}

// round 14
// speedup vs baseline: 1.5656x; 1.0579x over previous
#include <cuda_runtime.h>
#include <math.h>

#define KS2      4
#define BASIS    8
#define HIDDEN   16
#define M_NODES  64       // Chebyshev sample nodes
#define NCOEF    16       // polynomial terms (degree 15)

// Monomial coefficients a_0..a_{15} of F(t), t = 2*sigmoid(logit)-1.
// Read by patch_kernel through the constant-cache (LDC) path; written by
// build_coef_kernel through its global-memory backing address.
__constant__ float c_coef[NCOEF];

// Post-sigmoid pipeline at activation value a.
__device__ __forceinline__ float eval_f_act(float a,
                                            const float* __restrict__ basis,
                                            const float* __restrict__ w1,
                                            const float* __restrict__ b1,
                                            const float* __restrict__ w2,
                                            const float* __restrict__ b2)
{
    float feats[BASIS];
#pragma unroll
    for (int b = 0; b < BASIS; ++b) {
        float s = 0.0f;
#pragma unroll
        for (int j = 0; j < KS2; ++j) {
            float d = a - basis[b * KS2 + j];
            s = fmaf(d, d, s);
        }
        feats[b] = expf(-s);   // GAMMA = 1
    }

    float out = b2[0];
#pragma unroll
    for (int i = 0; i < HIDDEN; ++i) {
        float h = b1[i];
#pragma unroll
        for (int b = 0; b < BASIS; ++b)
            h = fmaf(feats[b], w1[b * HIDDEN + i], h);
        out = fmaf(tanhf(h), w2[i], out);
    }
    return out;
}

// One block, 512 threads:
//  phase 1: threads 0..63 sample F at the 64 Chebyshev nodes
//  phase 2: warp w (w < 16) computes Chebyshev coeff w (2 nodes/lane + reduce)
//  phase 3: warp 0 converts Chebyshev -> monomial with a shuffle recurrence
//           (doubles, no __syncthreads), writes straight to c_coef's backing.
__global__ void build_coef_kernel(const float* __restrict__ basis,
                                  const float* __restrict__ w1,
                                  const float* __restrict__ b1,
                                  const float* __restrict__ w2,
                                  const float* __restrict__ b2,
                                  float* __restrict__ coef_out)
{
    __shared__ float fv[M_NODES];
    __shared__ float cheb[NCOEF];

    int tid  = threadIdx.x;
    int wid  = tid >> 5;
    int lane = tid & 31;

    if (tid < M_NODES) {
        float t   = cospif(((float)tid + 0.5f) / (float)M_NODES);
        float act = 0.5f * (t + 1.0f);
        fv[tid] = eval_f_act(act, basis, w1, b1, w2, b2);
    }
    __syncthreads();

    if (wid < NCOEF) {
        float s = 0.0f;
#pragma unroll
        for (int r = 0; r < M_NODES / 32; ++r) {
            int j = lane + r * 32;
            s += fv[j] * cospif((float)wid * (((float)j + 0.5f) / (float)M_NODES));
        }
#pragma unroll
        for (int off = 16; off > 0; off >>= 1)
            s += __shfl_down_sync(0xFFFFFFFFu, s, off);
        if (lane == 0) {
            float scale = (wid == 0) ? (1.0f / M_NODES) : (2.0f / M_NODES);
            cheb[wid] = s * scale;
        }
    }
    __syncthreads();

    // Chebyshev -> monomial in warp 0. Lane p holds monomial coefficient p of
    // T_k: recurrence T_k = 2t*T_{k-1} - T_{k-2} is a lane shift-up.
    if (wid == 0) {
        double Tprev = (lane == 0) ? 1.0 : 0.0;   // T_0 coefficients
        double Tcur  = (lane == 1) ? 1.0 : 0.0;   // T_1 coefficients
        double acc   = (lane == 0) ? (double)cheb[0]
                     : (lane == 1) ? (double)cheb[1] : 0.0;
#pragma unroll
        for (int k = 2; k < NCOEF; ++k) {
            double sh = __shfl_up_sync(0xFFFFFFFFu, Tcur, 1);
            if (lane == 0) sh = 0.0;
            double nv = 2.0 * sh - Tprev;
            Tprev = Tcur;
            Tcur  = nv;
            acc  += (double)cheb[k] * nv;
        }
        if (lane < NCOEF)
            coef_out[lane] = (float)acc;
    }
}

// Streaming kernel, 4 patches/thread. Per patch: dot4 -> t = tanh(logit/2)
// -> even/odd Horner in t^2 with LDC coefficients (uniform path, zero L1
// wavefronts, minimal register pressure). No scattered memory anywhere.
__global__ void __launch_bounds__(256)
patch_kernel(const float* __restrict__ data,
             const float* __restrict__ conv_w,
             const float* __restrict__ conv_b,
             float* __restrict__ out,
             long long N)
{
    float cw0 = __ldg(conv_w + 0);
    float cw1 = __ldg(conv_w + 1);
    float cw2 = __ldg(conv_w + 2);
    float cw3 = __ldg(conv_w + 3);
    float cb  = __ldg(conv_b);

    long long tdx = (long long)blockIdx.x * blockDim.x + threadIdx.x;
    long long i0  = tdx * 4;

    if (i0 + 4 <= N) {
        const float4* dp = (const float4*)data + i0;
        float4 v[4];
#pragma unroll
        for (int p = 0; p < 4; ++p)
            v[p] = __ldg(dp + p);

        float t[4], t2[4];
#pragma unroll
        for (int p = 0; p < 4; ++p) {
            float logit = fmaf(v[p].x, cw0,
                          fmaf(v[p].y, cw1,
                          fmaf(v[p].z, cw2,
                          fmaf(v[p].w, cw3, cb))));
            float u = __expf(-fabsf(logit));                 // <= 1, no overflow
            float tt = __fdividef(1.0f - u, 1.0f + u);       // tanh(|logit|/2)
            t[p]  = copysignf(tt, logit);
            t2[p] = t[p] * t[p];
        }

        float e[4], o[4];
#pragma unroll
        for (int p = 0; p < 4; ++p) {
            e[p] = c_coef[NCOEF - 2];
            o[p] = c_coef[NCOEF - 1];
        }
#pragma unroll
        for (int k = NCOEF / 2 - 2; k >= 0; --k) {
            float ce = c_coef[2 * k];
            float co = c_coef[2 * k + 1];
#pragma unroll
            for (int p = 0; p < 4; ++p) {
                e[p] = fmaf(e[p], t2[p], ce);
                o[p] = fmaf(o[p], t2[p], co);
            }
        }

        float r[4];
#pragma unroll
        for (int p = 0; p < 4; ++p)
            r[p] = fmaf(t[p], o[p], e[p]);

        ((float4*)out)[tdx] = make_float4(r[0], r[1], r[2], r[3]);
    } else if (i0 < N) {
        for (long long i = i0; i < N; ++i) {
            float a0 = data[i * 4 + 0];
            float a1 = data[i * 4 + 1];
            float a2 = data[i * 4 + 2];
            float a3 = data[i * 4 + 3];
            float logit = fmaf(a0, cw0, fmaf(a1, cw1, fmaf(a2, cw2, fmaf(a3, cw3, cb))));
            float u  = __expf(-fabsf(logit));
            float tt = __fdividef(1.0f - u, 1.0f + u);
            float t  = copysignf(tt, logit);
            float t2 = t * t;
            float e = c_coef[NCOEF - 2];
            float o = c_coef[NCOEF - 1];
#pragma unroll
            for (int k = NCOEF / 2 - 2; k >= 0; --k) {
                e = fmaf(e, t2, c_coef[2 * k]);
                o = fmaf(o, t2, c_coef[2 * k + 1]);
            }
            out[i] = fmaf(t, o, e);
        }
    }
}

extern "C" void kernel_launch(void* const* d_in, const int* in_sizes, int n_in,
                              void* d_out, int out_size)
{
    const float* data   = (const float*)d_in[0];
    const float* conv_w = (const float*)d_in[1];
    const float* conv_b = (const float*)d_in[2];
    const float* basis  = (const float*)d_in[3];
    const float* w1     = (const float*)d_in[4];
    const float* b1     = (const float*)d_in[5];
    const float* w2     = (const float*)d_in[6];
    const float* b2     = (const float*)d_in[7];

    long long N = (long long)in_sizes[0] / KS2;   // in_sizes[0] = N * KS * KS

    // Backing address of c_coef: build kernel writes it directly; the
    // following launch's constant-cache reads see the fresh values
    // (caches are invalidated at launch boundaries). 2-node graph, no memcpy.
    static float* coef_dst = nullptr;
    if (!coef_dst) {
        void* p = nullptr;
        cudaGetSymbolAddress(&p, c_coef);
        coef_dst = (float*)p;
    }

    // 1) Fit monomial coefficients from this run's weights (1 small block).
    build_coef_kernel<<<1, 512>>>(basis, w1, b1, w2, b2, coef_dst);

    // 2) Streaming per-patch kernel, 4 patches per thread, full grid.
    long long nthreads = (N + 3) / 4;
    int threads = 256;
    long long blocks = (nthreads + threads - 1) / threads;
    if (blocks < 1) blocks = 1;
    patch_kernel<<<(unsigned int)blocks, threads>>>(data, conv_w, conv_b,
                                                    (float*)d_out, N);
}